// round 8
// baseline (speedup 1.0000x reference)
#include <cuda_runtime.h>
#include <cstdint>

#define THREADS 256
#define CAP 2048          // K2 fallback buffer (supports k <= CAP)
#define SCRATCH_CAP 512   // per-row candidate scratch (fast path needs k <= 512)
#define MAXROWS 8192

// Global scratch: 16 MB keys + counts (static __device__ arrays: no allocation)
__device__ unsigned g_keys[MAXROWS * SCRATCH_CAP];
__device__ int g_cnt[MAXROWS];

// Monotone float<->uint key mapping (total order matching IEEE float order)
__device__ __forceinline__ unsigned f2key(float f) {
    unsigned u = __float_as_uint(f);
    return (u & 0x80000000u) ? ~u : (u | 0x80000000u);
}
__device__ __forceinline__ float key2f(unsigned kk) {
    unsigned u = (kk & 0x80000000u) ? (kk ^ 0x80000000u) : ~kk;
    return __uint_as_float(u);
}

// Rare-path append of one float4's hits (as integer keys): one shared atomic per pack.
__device__ __forceinline__ void append_pack(float4 v, float t0, unsigned* s_key,
                                            int* s_cnt, int cap) {
    int h = (v.x > t0) + (v.y > t0) + (v.z > t0) + (v.w > t0);
    int base = atomicAdd(s_cnt, h);
    int p = base;
    if (v.x > t0) { if (p < cap) s_key[p] = f2key(v.x); p++; }
    if (v.y > t0) { if (p < cap) s_key[p] = f2key(v.y); p++; }
    if (v.z > t0) { if (p < cap) s_key[p] = f2key(v.z); p++; }
    if (v.w > t0) { if (p < cap) s_key[p] = f2key(v.w); p++; }
}

// Exact ranking of M keys (zero-padded to multiple of 4); writes ranks < k.
// rank_i = #{j<i : kj >= ki} + #{j>i : kj > ki}  == classic stable rank.
// Equal keys are interchangeable floats => output deterministic regardless of
// insertion order. Requires s_key 16B-aligned.
__device__ __forceinline__ void rank_and_write_keys(const unsigned* __restrict__ s_key,
                                                    int M, int k, float* __restrict__ outr,
                                                    int tid) {
    const int Mpad = (M + 3) & ~3;
    const uint4* __restrict__ k4 = (const uint4*)s_key;
    for (int i = tid; i < M; i += THREADS) {
        const unsigned ki = s_key[i];
        const int ib = i >> 2;
        int rank = 0;
        #pragma unroll 4
        for (int b = 0; b < ib; b++) {
            uint4 v = k4[b];
            rank += (v.x >= ki) + (v.y >= ki) + (v.z >= ki) + (v.w >= ki);
        }
        {
            uint4 v = k4[ib];
            int m = i & 3;
            rank += (0 < m) ? (v.x >= ki) : (v.x > ki);
            rank += (1 < m) ? (v.y >= ki) : (v.y > ki);
            rank += (2 < m) ? (v.z >= ki) : (v.z > ki);
            rank += (3 < m) ? (v.w >= ki) : (v.w > ki);
        }
        #pragma unroll 4
        for (int b = ib + 1; b < (Mpad >> 2); b++) {
            uint4 v = k4[b];
            rank += (v.x > ki) + (v.y > ki) + (v.z > ki) + (v.w > ki);
        }
        if (rank < k) outr[rank] = key2f(ki);
    }
}

// ===================== Kernel 1: pure streaming filter + dump =====================
__global__ void __launch_bounds__(THREADS)
topk_filter_kernel(const float* __restrict__ x, const int* __restrict__ kp,
                   long long n_x, long long out_n)
{
    __shared__ __align__(16) unsigned s_key[SCRATCH_CAP];
    __shared__ int s_cnt;

    const int k = *kp;
    const long long rows = out_n / k;
    const int row_len = (int)(n_x / rows);
    const int tid = threadIdx.x;
    const float t0 = 2.35f;

    for (long long r = blockIdx.x; r < rows; r += gridDim.x) {
        const float* __restrict__ xr = x + r * (long long)row_len;
        if (tid == 0) s_cnt = 0;
        __syncthreads();

        const int nv4 = row_len >> 2;
        const float4* __restrict__ x4 = (const float4*)xr;

        int i = tid;
        for (; i + 3 * THREADS < nv4; i += 4 * THREADS) {
            float4 a = __ldg(&x4[i]);
            float4 b = __ldg(&x4[i + THREADS]);
            float4 c = __ldg(&x4[i + 2 * THREADS]);
            float4 d = __ldg(&x4[i + 3 * THREADS]);
            float ma = fmaxf(fmaxf(a.x, a.y), fmaxf(a.z, a.w));
            float mb = fmaxf(fmaxf(b.x, b.y), fmaxf(b.z, b.w));
            float mc = fmaxf(fmaxf(c.x, c.y), fmaxf(c.z, c.w));
            float md = fmaxf(fmaxf(d.x, d.y), fmaxf(d.z, d.w));
            // one divergence region per 16 elements (taken ~14% of iterations)
            if (fmaxf(fmaxf(ma, mb), fmaxf(mc, md)) > t0) {
                if (ma > t0) append_pack(a, t0, s_key, &s_cnt, SCRATCH_CAP);
                if (mb > t0) append_pack(b, t0, s_key, &s_cnt, SCRATCH_CAP);
                if (mc > t0) append_pack(c, t0, s_key, &s_cnt, SCRATCH_CAP);
                if (md > t0) append_pack(d, t0, s_key, &s_cnt, SCRATCH_CAP);
            }
        }
        for (; i < nv4; i += THREADS) {
            float4 a = __ldg(&x4[i]);
            float ma = fmaxf(fmaxf(a.x, a.y), fmaxf(a.z, a.w));
            if (ma > t0) append_pack(a, t0, s_key, &s_cnt, SCRATCH_CAP);
        }
        for (int j = (nv4 << 2) + tid; j < row_len; j += THREADS) {
            float f = __ldg(&xr[j]);
            if (f > t0) { int s = atomicAdd(&s_cnt, 1); if (s < SCRATCH_CAP) s_key[s] = f2key(f); }
        }
        __syncthreads();

        if (r < MAXROWS) {
            int c = s_cnt;                   // may exceed SCRATCH_CAP: K2 detects + falls back
            int cc = min(c, SCRATCH_CAP);
            unsigned* gk = &g_keys[r * SCRATCH_CAP];
            for (int j = tid; j < cc; j += THREADS) gk[j] = s_key[j];
            if (tid == 0) g_cnt[r] = c;
        }
        __syncthreads();
    }
}

// ===================== Kernel 2: rank candidates (L2-resident) =====================
__global__ void __launch_bounds__(THREADS)
topk_rank_kernel(const float* __restrict__ x, const int* __restrict__ kp,
                 float* __restrict__ out, long long n_x, long long out_n)
{
    __shared__ __align__(16) unsigned s_key[CAP];
    __shared__ int s_cnt;
    __shared__ int s_c2;

    const int k = *kp;
    const long long rows = out_n / k;
    const int row_len = (int)(n_x / rows);
    const int tid = threadIdx.x;
    const int lane = tid & 31;

    for (long long r = blockIdx.x; r < rows; r += gridDim.x) {
        float* __restrict__ outr = out + r * (long long)k;
        const float* __restrict__ xr = x + r * (long long)row_len;

        int c = (r < MAXROWS) ? g_cnt[r] : -1;
        if (c >= k && c <= SCRATCH_CAP) {
            // ---- Fast path: candidates are a verified superset of top-k ----
            const unsigned* gk = &g_keys[r * SCRATCH_CAP];
            for (int j = tid; j < c; j += THREADS) s_key[j] = gk[j];
            int Mpad = (c + 3) & ~3;
            if (tid < Mpad - c) s_key[c + tid] = 0;    // pad ranks below everything
            __syncthreads();
            rank_and_write_keys(s_key, c, k, outr, tid);
        } else {
            // ---- Exact fallback: bisection for the k-th largest key over the row
            // (covers c<k, c>SCRATCH_CAP, r>=MAXROWS; any input, k<=CAP)
            long long lo = -1, hi = 0xFFFFFFFFll;
            while (lo + 1 < hi) {
                long long mid = (lo + hi) >> 1;
                unsigned tkey = (unsigned)mid;
                if (tid == 0) s_c2 = 0;
                __syncthreads();
                int local = 0;
                for (int j = tid; j < row_len; j += THREADS)
                    local += (f2key(__ldg(&xr[j])) > tkey) ? 1 : 0;
                #pragma unroll
                for (int o = 16; o; o >>= 1) local += __shfl_down_sync(0xFFFFFFFFu, local, o);
                if (lane == 0) atomicAdd(&s_c2, local);
                __syncthreads();
                int cc = s_c2;
                if (cc < k) hi = mid; else lo = mid;
                __syncthreads();
            }
            unsigned K = (unsigned)hi;                 // K = k-th largest key
            if (tid == 0) s_cnt = 0;
            __syncthreads();
            for (int j = tid; j < row_len; j += THREADS) {
                unsigned kf = f2key(__ldg(&xr[j]));
                if (kf > K) { int s = atomicAdd(&s_cnt, 1); if (s < CAP) s_key[s] = kf; }
            }
            __syncthreads();
            int M = s_cnt;                             // M < k <= CAP
            int Mpad = (M + 3) & ~3;
            if (tid < Mpad - M) s_key[M + tid] = 0;
            __syncthreads();
            rank_and_write_keys(s_key, M, k, outr, tid);
            float fk = key2f(K);                       // fill duplicates of the k-th value
            for (int j = M + tid; j < k; j += THREADS) outr[j] = fk;
        }
        __syncthreads();
    }
}

extern "C" void kernel_launch(void* const* d_in, const int* in_sizes, int n_in,
                              void* d_out, int out_size) {
    const float* x = (const float*)d_in[0];
    const int* kp = (const int*)d_in[1];
    long long n_x = (long long)in_sizes[0];
    long long out_n = (long long)out_size;
    int grid = (int)((out_n + 63) / 64);   // one CTA per row when k==64
    if (grid < 1) grid = 1;
    topk_filter_kernel<<<grid, THREADS>>>(x, kp, n_x, out_n);
    topk_rank_kernel<<<grid, THREADS>>>(x, kp, (float*)d_out, n_x, out_n);
}

// round 10
// speedup vs baseline: 1.3790x; 1.3790x over previous
#include <cuda_runtime.h>
#include <cstdint>

#define THREADS 256
#define CAP 2048          // candidate buffer capacity (supports k <= CAP)

// Monotone float<->uint key mapping (total order matching IEEE float order)
__device__ __forceinline__ unsigned f2key(float f) {
    unsigned u = __float_as_uint(f);
    return (u & 0x80000000u) ? ~u : (u | 0x80000000u);
}
__device__ __forceinline__ float key2f(unsigned kk) {
    unsigned u = (kk & 0x80000000u) ? (kk ^ 0x80000000u) : ~kk;
    return __uint_as_float(u);
}

// Rare-path append of one float4's hits (as integer keys): one shared atomic per pack.
__device__ __forceinline__ void append_pack(float4 v, float t0, unsigned* s_key, int* s_cnt) {
    int h = (v.x > t0) + (v.y > t0) + (v.z > t0) + (v.w > t0);
    int base = atomicAdd(s_cnt, h);
    int p = base;
    if (v.x > t0) { if (p < CAP) s_key[p] = f2key(v.x); p++; }
    if (v.y > t0) { if (p < CAP) s_key[p] = f2key(v.y); p++; }
    if (v.z > t0) { if (p < CAP) s_key[p] = f2key(v.z); p++; }
    if (v.w > t0) { if (p < CAP) s_key[p] = f2key(v.w); p++; }
}

// Exact ranking of M keys (zero-padded to multiple of 4); writes ranks < k.
// rank_i = #{j<i : kj >= ki} + #{j>i : kj > ki}  == classic stable rank.
// Equal keys are interchangeable floats => output deterministic regardless of
// the (atomic, unordered) insertion order. Requires s_key 16B-aligned.
__device__ __forceinline__ void rank_and_write_keys(const unsigned* __restrict__ s_key,
                                                    int M, int k, float* __restrict__ outr,
                                                    int tid) {
    const int Mpad = (M + 3) & ~3;
    const uint4* __restrict__ k4 = (const uint4*)s_key;
    for (int i = tid; i < M; i += THREADS) {
        const unsigned ki = s_key[i];
        const int ib = i >> 2;
        int rank = 0;
        #pragma unroll 4
        for (int b = 0; b < ib; b++) {
            uint4 v = k4[b];
            rank += (v.x >= ki) + (v.y >= ki) + (v.z >= ki) + (v.w >= ki);
        }
        {
            uint4 v = k4[ib];
            int m = i & 3;
            rank += (0 < m) ? (v.x >= ki) : (v.x > ki);
            rank += (1 < m) ? (v.y >= ki) : (v.y > ki);
            rank += (2 < m) ? (v.z >= ki) : (v.z > ki);
            rank += (3 < m) ? (v.w >= ki) : (v.w > ki);
        }
        #pragma unroll 4
        for (int b = ib + 1; b < (Mpad >> 2); b++) {
            uint4 v = k4[b];
            rank += (v.x > ki) + (v.y > ki) + (v.z > ki) + (v.w > ki);
        }
        if (rank < k) outr[rank] = key2f(ki);
    }
}

__global__ void __launch_bounds__(THREADS)
TopKPooling_20796231647786_kernel(
    const float* __restrict__ x, const int* __restrict__ kp,
    float* __restrict__ out, long long n_x, long long out_n)
{
    __shared__ __align__(16) unsigned s_key[CAP];
    __shared__ int s_cnt;
    __shared__ int s_c2;

    const int k = *kp;
    const long long rows = out_n / k;
    const int row_len = (int)(n_x / rows);
    const int tid = threadIdx.x;
    const int lane = tid & 31;

    for (long long r = blockIdx.x; r < rows; r += gridDim.x) {
        const float* __restrict__ xr = x + r * (long long)row_len;
        float* __restrict__ outr = out + r * (long long)k;

        // ---- Adaptive filter: tight threshold first (tiny candidate set);
        // retry once with a loose threshold if it under-collects (~0.4% of rows).
        int c = 0;
        #pragma unroll 1
        for (int pass = 0; pass < 2; pass++) {
            const float t0 = (pass == 0) ? 2.55f : 2.00f;
            if (tid == 0) s_cnt = 0;
            __syncthreads();

            const int nv4 = row_len >> 2;
            const float4* __restrict__ x4 = (const float4*)xr;
            int i = tid;
            for (; i + 3 * THREADS < nv4; i += 4 * THREADS) {
                float4 a = __ldg(&x4[i]);
                float4 b = __ldg(&x4[i + THREADS]);
                float4 c4 = __ldg(&x4[i + 2 * THREADS]);
                float4 d = __ldg(&x4[i + 3 * THREADS]);
                float ma = fmaxf(fmaxf(a.x, a.y), fmaxf(a.z, a.w));
                float mb = fmaxf(fmaxf(b.x, b.y), fmaxf(b.z, b.w));
                float mc = fmaxf(fmaxf(c4.x, c4.y), fmaxf(c4.z, c4.w));
                float md = fmaxf(fmaxf(d.x, d.y), fmaxf(d.z, d.w));
                if (ma > t0) append_pack(a, t0, s_key, &s_cnt);
                if (mb > t0) append_pack(b, t0, s_key, &s_cnt);
                if (mc > t0) append_pack(c4, t0, s_key, &s_cnt);
                if (md > t0) append_pack(d, t0, s_key, &s_cnt);
            }
            for (; i < nv4; i += THREADS) {
                float4 a = __ldg(&x4[i]);
                float ma = fmaxf(fmaxf(a.x, a.y), fmaxf(a.z, a.w));
                if (ma > t0) append_pack(a, t0, s_key, &s_cnt);
            }
            for (int j = (nv4 << 2) + tid; j < row_len; j += THREADS) {
                float f = __ldg(&xr[j]);
                if (f > t0) { int s = atomicAdd(&s_cnt, 1); if (s < CAP) s_key[s] = f2key(f); }
            }
            __syncthreads();
            c = s_cnt;
            if (c >= k) break;          // uniform decision (all threads read same s_cnt)
        }

        if (c >= k && c <= CAP) {
            // zero-pad to multiple of 4 (pad key 0 < any candidate key)
            int Mpad = (c + 3) & ~3;
            if (tid < Mpad - c) s_key[c + tid] = 0;
            __syncthreads();
            rank_and_write_keys(s_key, c, k, outr, tid);
        } else {
            // ---- Exact fallback: bisection for the k-th largest key (never taken on
            // the benchmark distribution; guarantees correctness for any input, k<=CAP)
            long long lo = -1, hi = 0xFFFFFFFFll;
            while (lo + 1 < hi) {
                long long mid = (lo + hi) >> 1;
                unsigned tkey = (unsigned)mid;
                if (tid == 0) s_c2 = 0;
                __syncthreads();
                int local = 0;
                for (int j = tid; j < row_len; j += THREADS)
                    local += (f2key(__ldg(&xr[j])) > tkey) ? 1 : 0;
                #pragma unroll
                for (int o = 16; o; o >>= 1) local += __shfl_down_sync(0xFFFFFFFFu, local, o);
                if (lane == 0) atomicAdd(&s_c2, local);
                __syncthreads();
                int cc = s_c2;
                if (cc < k) hi = mid; else lo = mid;
                __syncthreads();
            }
            unsigned K = (unsigned)hi;               // K = k-th largest key
            if (tid == 0) s_cnt = 0;
            __syncthreads();
            for (int j = tid; j < row_len; j += THREADS) {
                unsigned kf = f2key(__ldg(&xr[j]));
                if (kf > K) { int s = atomicAdd(&s_cnt, 1); if (s < CAP) s_key[s] = kf; }
            }
            __syncthreads();
            int M = s_cnt;                            // M < k <= CAP
            int Mpad = (M + 3) & ~3;
            if (tid < Mpad - M) s_key[M + tid] = 0;
            __syncthreads();
            rank_and_write_keys(s_key, M, k, outr, tid);
            float fk = key2f(K);                      // fill duplicates of the k-th value
            for (int j = M + tid; j < k; j += THREADS) outr[j] = fk;
        }
        __syncthreads();   // protect s_cnt/s_key reuse across row iterations
    }
}

extern "C" void kernel_launch(void* const* d_in, const int* in_sizes, int n_in,
                              void* d_out, int out_size) {
    const float* x = (const float*)d_in[0];
    const int* kp = (const int*)d_in[1];
    long long n_x = (long long)in_sizes[0];
    long long out_n = (long long)out_size;
    int grid = (int)((out_n + 63) / 64);   // one CTA per row when k==64
    if (grid < 1) grid = 1;
    TopKPooling_20796231647786_kernel<<<grid, THREADS>>>(x, kp, (float*)d_out, n_x, out_n);
}